// round 8
// baseline (speedup 1.0000x reference)
#include <cuda_runtime.h>
#include <cfloat>

// Batched Chamfer loss via uniform-grid exact nearest neighbor, 2 kernels.
// B=16, N=M=4096, 3D Gaussian points.
//
// bin_kernel: one block per (set,b). Counts, prefix-scan, and scatter all in
// shared memory; writes cell-sorted folded points (-2x,-2y,-2z,|t|^2) and
// per-cell starts to device globals. Leaves no state needing re-zeroing.
//
// query_kernel: queries read in BINNED (cell-sorted) order -> warp-coherent
// shell loops + broadcast loads. Exact NN: after scanning all cells with
// Chebyshev index distance <= s, unscanned points are >= s*H away, so stop
// when best d^2 <= (s*H)^2 (small safety margin). Last block folds weights
// and reduces to the scalar output.

constexpr int   B_    = 16;
constexpr int   N_    = 4096;
constexpr int   G     = 30;
constexpr int   CELLS = G * G * G;          // 27000
constexpr float H     = 0.35f;
constexpr float X0    = -5.25f;             // G*H = 10.5
constexpr float INVH  = 1.0f / H;

constexpr int QBS      = 256;
constexpr int QCHUNKS  = N_ / QBS;              // 16
constexpr int NQBLOCKS = 2 * B_ * QCHUNKS;      // 512
constexpr int NPART    = NQBLOCKS;

constexpr int BIN_THREADS = 1024;
constexpr int PPT         = N_ / BIN_THREADS;   // 4 points per thread
constexpr int SMEM_BIN    = (CELLS + BIN_THREADS) * 4;  // 112096 B

__device__ float4 g_binned[2 * B_ * N_];        // cell-sorted folded points
__device__ int    g_starts[2 * B_ * (CELLS + 1)];
__device__ float  g_partial[NPART];
__device__ int    g_done;                        // zero-init; reset each replay

__device__ __forceinline__ int cell_of(float v) {
    int c = (int)floorf((v - X0) * INVH);
    return min(max(c, 0), G - 1);
}

// ---------------- binning: count + scan + scatter in one block ----------------

__global__ void __launch_bounds__(BIN_THREADS)
bin_kernel(const float* __restrict__ src, const float* __restrict__ tgt)
{
    extern __shared__ int s_mem[];
    int* scnt  = s_mem;            // [CELLS]  counts -> then exclusive starts
    int* spart = s_mem + CELLS;    // [BIN_THREADS] scan workspace

    const int sb  = blockIdx.x;                 // 0..31 = set*16 + b
    const int set = sb >> 4, b = sb & 15;
    const float* __restrict__ pts = (set == 0 ? src : tgt) + (size_t)b * N_ * 3;
    const int t = threadIdx.x;

    for (int i = t; i < CELLS; i += BIN_THREADS) scnt[i] = 0;
    __syncthreads();

    // Count; cache coords + cell ids in registers for the scatter pass.
    float px[PPT], py[PPT], pz[PPT];
    int   pc[PPT];
#pragma unroll
    for (int r = 0; r < PPT; ++r) {
        const float* p = pts + (size_t)(r * BIN_THREADS + t) * 3;
        px[r] = p[0]; py[r] = p[1]; pz[r] = p[2];
        pc[r] = (cell_of(pz[r]) * G + cell_of(py[r])) * G + cell_of(px[r]);
        atomicAdd(&scnt[pc[r]], 1);
    }
    __syncthreads();

    // Exclusive scan over CELLS: serial-local (27/thread) + Hillis-Steele.
    const int base = t * 27;                    // 1024*27 = 27648 >= 27000
    int sum = 0;
#pragma unroll
    for (int i = 0; i < 27; ++i) {
        const int c = base + i;
        if (c < CELLS) sum += scnt[c];
    }
    spart[t] = sum;
    __syncthreads();
    for (int d = 1; d < BIN_THREADS; d <<= 1) {
        int v = (t >= d) ? spart[t - d] : 0;
        __syncthreads();
        spart[t] += v;
        __syncthreads();
    }
    int run = spart[t] - sum;                   // exclusive offset
    int* starts = g_starts + sb * (CELLS + 1);
#pragma unroll
    for (int i = 0; i < 27; ++i) {
        const int c = base + i;
        if (c < CELLS) {
            const int cnt = scnt[c];
            starts[c] = run;
            scnt[c]   = run;                    // smem now holds write cursors
            run += cnt;
        }
    }
    if (t == BIN_THREADS - 1) starts[CELLS] = spart[BIN_THREADS - 1]; // == N_
    __syncthreads();

    // Scatter folded points into cell-sorted order.
#pragma unroll
    for (int r = 0; r < PPT; ++r) {
        const int pos = atomicAdd(&scnt[pc[r]], 1);
        g_binned[sb * N_ + pos] =
            make_float4(-2.0f * px[r], -2.0f * py[r], -2.0f * pz[r],
                        px[r] * px[r] + py[r] * py[r] + pz[r] * pz[r]);
    }
}

// ---------------- query: exact NN, queries in binned order ----------------

__global__ void __launch_bounds__(QBS)
query_kernel(const float* __restrict__ weights, float* __restrict__ out)
{
    const int dir = blockIdx.z;                 // 0: src->tgt, 1: tgt->src
    const int b   = blockIdx.y;
    const int tid = threadIdx.x;

    const int qsb  = dir * B_ + b;              // query set (== dir's set)
    const int dbsb = (1 - dir) * B_ + b;        // database set
    const int pos  = blockIdx.x * QBS + tid;

    const float4 qt = g_binned[qsb * N_ + pos];
    const float qx = -0.5f * qt.x, qy = -0.5f * qt.y, qz = -0.5f * qt.z;
    const float q2 = qt.w;

    const float4* __restrict__ pts    = g_binned + dbsb * N_;
    const int*    __restrict__ starts = g_starts + dbsb * (CELLS + 1);

    const int cx = cell_of(qx), cy = cell_of(qy), cz = cell_of(qz);

    float dbest = FLT_MAX;                      // folded (= d^2 - q2)

    // Phase 1: full 3x3x3 cube (Chebyshev <= 1), 9 contiguous x-runs.
    {
        const int zlo = max(cz - 1, 0), zhi = min(cz + 1, G - 1);
        const int ylo = max(cy - 1, 0), yhi = min(cy + 1, G - 1);
        const int xlo = max(cx - 1, 0), xhi = min(cx + 1, G - 1);
        for (int z = zlo; z <= zhi; ++z)
            for (int y = ylo; y <= yhi; ++y) {
                const int rowBase = (z * G + y) * G;
                const int p1 = starts[rowBase + xhi + 1];
                for (int p = starts[rowBase + xlo]; p < p1; ++p) {
                    const float4 tp = pts[p];
                    dbest = fminf(dbest,
                            fmaf(qx, tp.x, fmaf(qy, tp.y, fmaf(qz, tp.z, tp.w))));
                }
            }
    }

    // Phase 2: expanding shell surfaces s >= 2 (rare; ~3% of queries).
    if (q2 + dbest > H * H - 1e-4f) {
        for (int s = 2; s < G; ++s) {
            for (int dz = -s; dz <= s; ++dz) {
                const int z = cz + dz;
                if ((unsigned)z >= (unsigned)G) continue;
                const bool face_z = (dz == -s) | (dz == s);
                for (int dy = -s; dy <= s; ++dy) {
                    const int y = cy + dy;
                    if ((unsigned)y >= (unsigned)G) continue;
                    const int rowBase = (z * G + y) * G;
                    if (face_z | (dy == -s) | (dy == s)) {
                        const int xlo = max(cx - s, 0), xhi = min(cx + s, G - 1);
                        const int p1 = starts[rowBase + xhi + 1];
                        for (int p = starts[rowBase + xlo]; p < p1; ++p) {
                            const float4 tp = pts[p];
                            dbest = fminf(dbest,
                                    fmaf(qx, tp.x, fmaf(qy, tp.y, fmaf(qz, tp.z, tp.w))));
                        }
                    } else {
                        int x = cx - s;
                        if (x >= 0) {
                            const int p1 = starts[rowBase + x + 1];
                            for (int p = starts[rowBase + x]; p < p1; ++p) {
                                const float4 tp = pts[p];
                                dbest = fminf(dbest,
                                        fmaf(qx, tp.x, fmaf(qy, tp.y, fmaf(qz, tp.z, tp.w))));
                            }
                        }
                        x = cx + s;
                        if (x < G) {
                            const int p1 = starts[rowBase + x + 1];
                            for (int p = starts[rowBase + x]; p < p1; ++p) {
                                const float4 tp = pts[p];
                                dbest = fminf(dbest,
                                        fmaf(qx, tp.x, fmaf(qy, tp.y, fmaf(qz, tp.z, tp.w))));
                            }
                        }
                    }
                }
            }
            const float sh_ = (float)s * H;     // all cells <= s scanned
            if (q2 + dbest <= sh_ * sh_ - 1e-4f) break;
        }
    }

    const float res = fmaxf(q2 + dbest, 0.0f);

    // Block reduction of this chunk's sum.
    __shared__ float s_red[QBS];
    __shared__ int   s_last;
    s_red[tid] = res;
    __syncthreads();
#pragma unroll
    for (int st = QBS / 2; st > 0; st >>= 1) {
        if (tid < st) s_red[tid] += s_red[tid + st];
        __syncthreads();
    }
    if (tid == 0) {
        g_partial[dir * (B_ * QCHUNKS) + b * QCHUNKS + blockIdx.x] = s_red[0];
        __threadfence();
        s_last = (atomicAdd(&g_done, 1) == NQBLOCKS - 1) ? 1 : 0;
    }
    __syncthreads();

    // Last block: fold weights, reduce 512 partials to the scalar loss.
    if (s_last) {
        __threadfence();
        float a = 0.0f;
#pragma unroll
        for (int k = tid; k < NPART; k += QBS) {
            const int bb = (k >> 4) & 15;       // index = dir*256 + b*16 + chunk
            a += g_partial[k] * weights[bb];
        }
        s_red[tid] = a;
        __syncthreads();
#pragma unroll
        for (int st = QBS / 2; st > 0; st >>= 1) {
            if (tid < st) s_red[tid] += s_red[tid + st];
            __syncthreads();
        }
        if (tid == 0) {
            out[0] = s_red[0] * (1.0f / (16.0f * 4096.0f));
            g_done = 0;                          // reset for next graph replay
        }
    }
}

extern "C" void kernel_launch(void* const* d_in, const int* in_sizes, int n_in,
                              void* d_out, int out_size)
{
    const float* src = (const float*)d_in[0];   // [16, 4096, 3]
    const float* tgt = (const float*)d_in[1];   // [16, 4096, 3]
    const float* w   = (const float*)d_in[2];   // [16]

    static bool attr_set = false;
    if (!attr_set) {
        cudaFuncSetAttribute(bin_kernel,
                             cudaFuncAttributeMaxDynamicSharedMemorySize,
                             SMEM_BIN);
        attr_set = true;
    }

    bin_kernel<<<2 * B_, BIN_THREADS, SMEM_BIN>>>(src, tgt);
    query_kernel<<<dim3(QCHUNKS, B_, 2), QBS>>>(w, (float*)d_out);
}

// round 11
// speedup vs baseline: 1.0993x; 1.0993x over previous
#include <cuda_runtime.h>
#include <cfloat>

// Batched Chamfer loss via uniform-grid exact nearest neighbor, 3 kernels.
// bin_kernel:   count+scan+scatter per (set,b) in smem -> cell-sorted folded
//               points (-2x,-2y,-2z,|t|^2) + per-cell starts. Resets counter.
// query_kernel: PERSISTENT warps steal 32-query units off a global counter.
//               Queries read in binned (cell-sorted) order -> warp-coherent;
//               phase 1 prefetches all 9 row ranges (MLP) then scans 3x3x3;
//               phase 2 expands Chebyshev shells until d^2 <= (s*H)^2.
// finalize:     deterministic weighted tree-reduction of 4096 unit sums.

constexpr int   B_    = 16;
constexpr int   N_    = 4096;
constexpr int   G     = 30;
constexpr int   CELLS = G * G * G;          // 27000
constexpr float H     = 0.35f;
constexpr float X0    = -5.25f;             // G*H = 10.5
constexpr float INVH  = 1.0f / H;

constexpr int BIN_THREADS = 1024;
constexpr int PPT         = N_ / BIN_THREADS;           // 4
constexpr int SMEM_BIN    = (CELLS + BIN_THREADS) * 4;  // 112096 B

constexpr int NQ      = 2 * B_ * N_;        // 131072 queries
constexpr int NUNITS  = NQ / 32;            // 4096 warp units
constexpr int QTHREADS = 256;
constexpr int QBLOCKS  = 296;               // 2 per SM

__device__ float4 g_binned[2 * B_ * N_];    // cell-sorted folded points
__device__ int    g_starts[2 * B_ * (CELLS + 1)];
__device__ float  g_usum[NUNITS];
__device__ int    g_qhead;                  // work-stealing counter

__device__ __forceinline__ int cell_of(float v) {
    int c = (int)floorf((v - X0) * INVH);
    return min(max(c, 0), G - 1);
}

// ---------------- binning: count + scan + scatter in one block ----------------

__global__ void __launch_bounds__(BIN_THREADS)
bin_kernel(const float* __restrict__ src, const float* __restrict__ tgt)
{
    extern __shared__ int s_mem[];
    int* scnt  = s_mem;            // [CELLS] counts -> then write cursors
    int* spart = s_mem + CELLS;    // [BIN_THREADS] scan workspace

    const int sb  = blockIdx.x;                 // 0..31 = set*16 + b
    const int set = sb >> 4, b = sb & 15;
    const float* __restrict__ pts = (set == 0 ? src : tgt) + (size_t)b * N_ * 3;
    const int t = threadIdx.x;

    if (sb == 0 && t == 0) g_qhead = 0;         // reset steal counter per replay

    for (int i = t; i < CELLS; i += BIN_THREADS) scnt[i] = 0;
    __syncthreads();

    float px[PPT], py[PPT], pz[PPT];
    int   pc[PPT];
#pragma unroll
    for (int r = 0; r < PPT; ++r) {
        const float* p = pts + (size_t)(r * BIN_THREADS + t) * 3;
        px[r] = p[0]; py[r] = p[1]; pz[r] = p[2];
        pc[r] = (cell_of(pz[r]) * G + cell_of(py[r])) * G + cell_of(px[r]);
        atomicAdd(&scnt[pc[r]], 1);
    }
    __syncthreads();

    // Exclusive scan over CELLS: 27 serial per thread + Hillis-Steele.
    const int base = t * 27;                    // 1024*27 >= 27000
    int sum = 0;
#pragma unroll
    for (int i = 0; i < 27; ++i) {
        const int c = base + i;
        if (c < CELLS) sum += scnt[c];
    }
    spart[t] = sum;
    __syncthreads();
    for (int d = 1; d < BIN_THREADS; d <<= 1) {
        int v = (t >= d) ? spart[t - d] : 0;
        __syncthreads();
        spart[t] += v;
        __syncthreads();
    }
    int run = spart[t] - sum;
    int* starts = g_starts + sb * (CELLS + 1);
#pragma unroll
    for (int i = 0; i < 27; ++i) {
        const int c = base + i;
        if (c < CELLS) {
            const int cnt = scnt[c];
            starts[c] = run;
            scnt[c]   = run;                    // smem becomes write cursor
            run += cnt;
        }
    }
    if (t == BIN_THREADS - 1) starts[CELLS] = spart[BIN_THREADS - 1];
    __syncthreads();

#pragma unroll
    for (int r = 0; r < PPT; ++r) {
        const int pos = atomicAdd(&scnt[pc[r]], 1);
        g_binned[sb * N_ + pos] =
            make_float4(-2.0f * px[r], -2.0f * py[r], -2.0f * pz[r],
                        px[r] * px[r] + py[r] * py[r] + pz[r] * pz[r]);
    }
}

// ---------------- query: persistent warps, work stealing ----------------

__global__ void __launch_bounds__(QTHREADS)
query_kernel()
{
    const int lane = threadIdx.x & 31;

    while (true) {
        int u = 0;
        if (lane == 0) u = atomicAdd(&g_qhead, 1);
        u = __shfl_sync(0xffffffffu, u, 0);
        if (u >= NUNITS) break;

        const int qsb  = u >> 7;                // 128 units per (set,b)
        const int dbsb = qsb ^ 16;              // opposite set, same b
        const int pos  = ((u & 127) << 5) + lane;

        const float4 qt = g_binned[qsb * N_ + pos];
        const float qx = -0.5f * qt.x, qy = -0.5f * qt.y, qz = -0.5f * qt.z;
        const float q2 = qt.w;

        const float4* __restrict__ pts    = g_binned + dbsb * N_;
        const int*    __restrict__ starts = g_starts + dbsb * (CELLS + 1);

        const int cx = cell_of(qx), cy = cell_of(qy), cz = cell_of(qz);
        float dbest = FLT_MAX;                  // folded (= d^2 - q2)

        // Phase 1: 3x3x3 cube; prefetch all 9 row ranges first (MLP).
        {
            const int xlo = max(cx - 1, 0), xhi = min(cx + 1, G - 1);
            int p0[9], p1[9];
#pragma unroll
            for (int i = 0; i < 9; ++i) {
                const int z = cz + i / 3 - 1, y = cy + i % 3 - 1;
                const bool ok = ((unsigned)z < (unsigned)G) &
                                ((unsigned)y < (unsigned)G);
                const int zc = min(max(z, 0), G - 1);
                const int yc = min(max(y, 0), G - 1);
                const int rb = (zc * G + yc) * G;
                const int a  = starts[rb + xlo];       // always in-bounds
                const int e  = starts[rb + xhi + 1];
                p0[i] = ok ? a : 0;
                p1[i] = ok ? e : 0;
            }
#pragma unroll
            for (int i = 0; i < 9; ++i) {
                for (int p = p0[i]; p < p1[i]; ++p) {
                    const float4 tp = pts[p];
                    dbest = fminf(dbest,
                            fmaf(qx, tp.x, fmaf(qy, tp.y, fmaf(qz, tp.z, tp.w))));
                }
            }
        }

        // Phase 2: expanding shell surfaces s >= 2 (rare).
        if (q2 + dbest > H * H - 1e-4f) {
            for (int s = 2; s < G; ++s) {
                for (int dz = -s; dz <= s; ++dz) {
                    const int z = cz + dz;
                    if ((unsigned)z >= (unsigned)G) continue;
                    const bool face_z = (dz == -s) | (dz == s);
                    for (int dy = -s; dy <= s; ++dy) {
                        const int y = cy + dy;
                        if ((unsigned)y >= (unsigned)G) continue;
                        const int rowBase = (z * G + y) * G;
                        if (face_z | (dy == -s) | (dy == s)) {
                            const int xlo = max(cx - s, 0);
                            const int xhi = min(cx + s, G - 1);
                            const int p1 = starts[rowBase + xhi + 1];
                            for (int p = starts[rowBase + xlo]; p < p1; ++p) {
                                const float4 tp = pts[p];
                                dbest = fminf(dbest,
                                        fmaf(qx, tp.x, fmaf(qy, tp.y, fmaf(qz, tp.z, tp.w))));
                            }
                        } else {
                            int x = cx - s;
                            if (x >= 0) {
                                const int p1 = starts[rowBase + x + 1];
                                for (int p = starts[rowBase + x]; p < p1; ++p) {
                                    const float4 tp = pts[p];
                                    dbest = fminf(dbest,
                                            fmaf(qx, tp.x, fmaf(qy, tp.y, fmaf(qz, tp.z, tp.w))));
                                }
                            }
                            x = cx + s;
                            if (x < G) {
                                const int p1 = starts[rowBase + x + 1];
                                for (int p = starts[rowBase + x]; p < p1; ++p) {
                                    const float4 tp = pts[p];
                                    dbest = fminf(dbest,
                                            fmaf(qx, tp.x, fmaf(qy, tp.y, fmaf(qz, tp.z, tp.w))));
                                }
                            }
                        }
                    }
                }
                const float sh_ = (float)s * H;
                if (q2 + dbest <= sh_ * sh_ - 1e-4f) break;
            }
        }

        const float res = fmaxf(q2 + dbest, 0.0f);

        // Deterministic warp sum (fixed tree), one store per unit.
        float wsum = res;
#pragma unroll
        for (int off = 16; off > 0; off >>= 1)
            wsum += __shfl_down_sync(0xffffffffu, wsum, off);
        if (lane == 0) g_usum[u] = wsum;
    }
}

// ---------------- finalize: deterministic weighted reduction ----------------

__global__ void __launch_bounds__(1024)
finalize_kernel(const float* __restrict__ weights, float* __restrict__ out)
{
    const int t = threadIdx.x;
    __shared__ float s[1024];
    float a = 0.0f;
#pragma unroll
    for (int k = 0; k < NUNITS / 1024; ++k) {
        const int u = t + k * 1024;
        a += g_usum[u] * weights[(u >> 7) & 15];
    }
    s[t] = a;
    __syncthreads();
#pragma unroll
    for (int st = 512; st > 0; st >>= 1) {
        if (t < st) s[t] += s[t + st];
        __syncthreads();
    }
    if (t == 0) out[0] = s[0] * (1.0f / (16.0f * 4096.0f));
}

extern "C" void kernel_launch(void* const* d_in, const int* in_sizes, int n_in,
                              void* d_out, int out_size)
{
    const float* src = (const float*)d_in[0];   // [16, 4096, 3]
    const float* tgt = (const float*)d_in[1];   // [16, 4096, 3]
    const float* w   = (const float*)d_in[2];   // [16]

    static bool attr_set = false;
    if (!attr_set) {
        cudaFuncSetAttribute(bin_kernel,
                             cudaFuncAttributeMaxDynamicSharedMemorySize,
                             SMEM_BIN);
        attr_set = true;
    }

    bin_kernel<<<2 * B_, BIN_THREADS, SMEM_BIN>>>(src, tgt);
    query_kernel<<<QBLOCKS, QTHREADS>>>();
    finalize_kernel<<<1, 1024>>>(w, (float*)d_out);
}

// round 12
// speedup vs baseline: 1.4525x; 1.3213x over previous
#include <cuda_runtime.h>
#include <cfloat>

// Batched Chamfer loss via uniform grid (bulk) + dense brute force (tail).
// B=16, N=M=4096, 3D Gaussian points.
//
// bin_kernel:   per (set,b): count + shfl-scan + scatter in smem ->
//               cell-sorted folded points (-2x,-2y,-2z,|t|^2) + cell starts.
// phase1_kernel: work-stealing warps; each query scans ONLY its 3x3x3 cell
//               cube (prefetched row ranges). Exact iff d^2 <= H^2 - eps
//               (all non-cube points are >= H away). Unresolved queries are
//               compacted into per-(set,b) lists. No shell loops -> no
//               divergent tail walks.
// tail_kernel:  one block per (set,b); db staged in smem; one WARP per
//               unresolved query; exact min via shfl fminf tree.
// finalize:     deterministic weighted reduction of 131072 per-query values.

constexpr int   B_    = 16;
constexpr int   N_    = 4096;
constexpr int   G     = 20;
constexpr int   CELLS = G * G * G;          // 8000
constexpr float H     = 0.35f;
constexpr float X0    = -3.5f;              // G*H = 7.0 -> [-3.5, 3.5]
constexpr float INVH  = 1.0f / H;
constexpr float RES_T = H * H - 1e-4f;      // resolved threshold

constexpr int BIN_THREADS = 1024;
constexpr int PPT         = N_ / BIN_THREADS;   // 4

constexpr int NQ       = 2 * B_ * N_;       // 131072
constexpr int NUNITS   = NQ / 32;           // 4096 warp units
constexpr int QTHREADS = 256;
constexpr int QBLOCKS  = 296;

constexpr int TAIL_SMEM = N_ * 16;          // 64 KB float4 db tile

__device__ float4 g_binned[2 * B_ * N_];    // cell-sorted folded points
__device__ int    g_starts[2 * B_ * (CELLS + 1)];
__device__ float  g_res[NQ];                // per-query clamped NN d^2
__device__ int    g_tail[2 * B_ * N_];      // unresolved positions per (set,b)
__device__ int    g_tailcnt[2 * B_];
__device__ int    g_qhead;                  // work-stealing counter

__device__ __forceinline__ int cell_of(float v) {
    int c = (int)floorf((v - X0) * INVH);
    return min(max(c, 0), G - 1);
}

// ---------------- binning ----------------

__global__ void __launch_bounds__(BIN_THREADS)
bin_kernel(const float* __restrict__ src, const float* __restrict__ tgt)
{
    __shared__ int scnt[CELLS];             // counts -> write cursors
    __shared__ int s_wsum[32];

    const int sb  = blockIdx.x;             // 0..31 = set*16 + b
    const int set = sb >> 4, b = sb & 15;
    const float* __restrict__ pts = (set == 0 ? src : tgt) + (size_t)b * N_ * 3;
    const int t = threadIdx.x, lane = t & 31, wid = t >> 5;

    if (sb == 0) {                          // reset per-replay state
        if (t < 2 * B_) g_tailcnt[t] = 0;
        if (t == 2 * B_) g_qhead = 0;
    }

#pragma unroll
    for (int i = 0; i < 8; ++i) {
        const int c = t * 8 + i;
        if (c < CELLS) scnt[c] = 0;
    }
    __syncthreads();

    // Count; cache coords + cells in registers for the scatter pass.
    float px[PPT], py[PPT], pz[PPT];
    int   pc[PPT];
#pragma unroll
    for (int r = 0; r < PPT; ++r) {
        const float* p = pts + (size_t)(r * BIN_THREADS + t) * 3;
        px[r] = p[0]; py[r] = p[1]; pz[r] = p[2];
        pc[r] = (cell_of(pz[r]) * G + cell_of(py[r])) * G + cell_of(px[r]);
        atomicAdd(&scnt[pc[r]], 1);
    }
    __syncthreads();

    // Exclusive scan over CELLS: 8 serial/thread + shfl warp scans.
    int local[8], sum = 0;
#pragma unroll
    for (int i = 0; i < 8; ++i) {
        const int c = t * 8 + i;
        local[i] = (c < CELLS) ? scnt[c] : 0;
        sum += local[i];
    }
    int incl = sum;
#pragma unroll
    for (int off = 1; off < 32; off <<= 1) {
        const int v = __shfl_up_sync(0xffffffffu, incl, off);
        if (lane >= off) incl += v;
    }
    if (lane == 31) s_wsum[wid] = incl;
    __syncthreads();
    if (wid == 0) {
        const int v = s_wsum[lane];
        int inc2 = v;
#pragma unroll
        for (int off = 1; off < 32; off <<= 1) {
            const int u = __shfl_up_sync(0xffffffffu, inc2, off);
            if (lane >= off) inc2 += u;
        }
        s_wsum[lane] = inc2 - v;            // exclusive warp offsets
    }
    __syncthreads();

    int run = s_wsum[wid] + incl - sum;     // thread's exclusive prefix
    int* starts = g_starts + sb * (CELLS + 1);
#pragma unroll
    for (int i = 0; i < 8; ++i) {
        const int c = t * 8 + i;
        if (c < CELLS) {
            starts[c] = run;
            scnt[c]   = run;                // smem becomes write cursor
            run += local[i];
        }
    }
    if (t == 0) starts[CELLS] = N_;
    __syncthreads();

#pragma unroll
    for (int r = 0; r < PPT; ++r) {
        const int pos = atomicAdd(&scnt[pc[r]], 1);
        g_binned[sb * N_ + pos] =
            make_float4(-2.0f * px[r], -2.0f * py[r], -2.0f * pz[r],
                        px[r] * px[r] + py[r] * py[r] + pz[r] * pz[r]);
    }
}

// ---------------- phase 1: 3x3x3 cube only ----------------

__global__ void __launch_bounds__(QTHREADS)
phase1_kernel()
{
    const int lane = threadIdx.x & 31;

    while (true) {
        int u = 0;
        if (lane == 0) u = atomicAdd(&g_qhead, 1);
        u = __shfl_sync(0xffffffffu, u, 0);
        if (u >= NUNITS) break;

        const int qsb  = u >> 7;            // 128 units per (set,b)
        const int dbsb = qsb ^ 16;
        const int pos  = ((u & 127) << 5) + lane;

        const float4 qt = g_binned[qsb * N_ + pos];
        const float qx = -0.5f * qt.x, qy = -0.5f * qt.y, qz = -0.5f * qt.z;
        const float q2 = qt.w;

        const float4* __restrict__ pts    = g_binned + dbsb * N_;
        const int*    __restrict__ starts = g_starts + dbsb * (CELLS + 1);

        const int cx = cell_of(qx), cy = cell_of(qy), cz = cell_of(qz);
        const int xlo = max(cx - 1, 0), xhi = min(cx + 1, G - 1);

        // Prefetch all 9 row ranges (high MLP), then scan.
        int p0[9], p1[9];
#pragma unroll
        for (int i = 0; i < 9; ++i) {
            const int z = cz + i / 3 - 1, y = cy + i % 3 - 1;
            const bool ok = ((unsigned)z < (unsigned)G) &
                            ((unsigned)y < (unsigned)G);
            const int zc = min(max(z, 0), G - 1);
            const int yc = min(max(y, 0), G - 1);
            const int rb = (zc * G + yc) * G;
            const int a  = starts[rb + xlo];
            const int e  = starts[rb + xhi + 1];
            p0[i] = ok ? a : 0;
            p1[i] = ok ? e : 0;
        }

        float dbest = FLT_MAX;              // folded (= d^2 - q2)
#pragma unroll
        for (int i = 0; i < 9; ++i) {
            for (int p = p0[i]; p < p1[i]; ++p) {
                const float4 tp = pts[p];
                dbest = fminf(dbest,
                        fmaf(qx, tp.x, fmaf(qy, tp.y, fmaf(qz, tp.z, tp.w))));
            }
        }

        const float d2 = q2 + dbest;
        g_res[qsb * N_ + pos] = fmaxf(d2, 0.0f);   // tail overwrites if needed

        // Compact unresolved queries (warp-aggregated atomic).
        const bool unres = !(d2 <= RES_T);
        const unsigned m = __ballot_sync(0xffffffffu, unres);
        if (m) {
            const int leader = __ffs(m) - 1;
            int base = 0;
            if (lane == leader) base = atomicAdd(&g_tailcnt[qsb], __popc(m));
            base = __shfl_sync(0xffffffffu, base, leader);
            if (unres) {
                const int off = __popc(m & ((1u << lane) - 1u));
                g_tail[qsb * N_ + base + off] = pos;
            }
        }
    }
}

// ---------------- tail: dense brute force, one warp per query ----------------

__global__ void __launch_bounds__(QTHREADS)
tail_kernel()
{
    extern __shared__ float4 s_db[];        // 64 KB: full db for this (set,b)
    const int sb   = blockIdx.x;            // query set
    const int dbsb = sb ^ 16;
    const int tid  = threadIdx.x;
    const int lane = tid & 31, wid = tid >> 5;

    for (int i = tid; i < N_; i += QTHREADS)
        s_db[i] = g_binned[dbsb * N_ + i];
    __syncthreads();

    const int n = g_tailcnt[sb];
    for (int j = wid; j < n; j += QTHREADS / 32) {
        const int pos = g_tail[sb * N_ + j];
        const float4 qt = g_binned[sb * N_ + pos];
        const float qx = -0.5f * qt.x, qy = -0.5f * qt.y, qz = -0.5f * qt.z;

        float m = FLT_MAX;
#pragma unroll 4
        for (int k = lane; k < N_; k += 32) {
            const float4 tp = s_db[k];
            m = fminf(m, fmaf(qx, tp.x, fmaf(qy, tp.y, fmaf(qz, tp.z, tp.w))));
        }
#pragma unroll
        for (int off = 16; off > 0; off >>= 1)
            m = fminf(m, __shfl_xor_sync(0xffffffffu, m, off));
        if (lane == 0)
            g_res[sb * N_ + pos] = fmaxf(qt.w + m, 0.0f);
    }
}

// ---------------- finalize ----------------

__global__ void __launch_bounds__(1024)
finalize_kernel(const float* __restrict__ weights, float* __restrict__ out)
{
    const int t = threadIdx.x;
    __shared__ float s[1024];
    float a = 0.0f;
#pragma unroll
    for (int k = 0; k < NQ / 1024; ++k) {
        const int u = t + k * 1024;
        a += g_res[u] * weights[(u >> 12) & 15];
    }
    s[t] = a;
    __syncthreads();
#pragma unroll
    for (int st = 512; st > 0; st >>= 1) {
        if (t < st) s[t] += s[t + st];
        __syncthreads();
    }
    if (t == 0) out[0] = s[0] * (1.0f / (16.0f * 4096.0f));
}

extern "C" void kernel_launch(void* const* d_in, const int* in_sizes, int n_in,
                              void* d_out, int out_size)
{
    const float* src = (const float*)d_in[0];   // [16, 4096, 3]
    const float* tgt = (const float*)d_in[1];   // [16, 4096, 3]
    const float* w   = (const float*)d_in[2];   // [16]

    static bool attr_set = false;
    if (!attr_set) {
        cudaFuncSetAttribute(tail_kernel,
                             cudaFuncAttributeMaxDynamicSharedMemorySize,
                             TAIL_SMEM);
        attr_set = true;
    }

    bin_kernel<<<2 * B_, BIN_THREADS>>>(src, tgt);
    phase1_kernel<<<QBLOCKS, QTHREADS>>>();
    tail_kernel<<<2 * B_, QTHREADS, TAIL_SMEM>>>();
    finalize_kernel<<<1, 1024>>>(w, (float*)d_out);
}

// round 13
// speedup vs baseline: 1.5145x; 1.0427x over previous
#include <cuda_runtime.h>
#include <cfloat>

// Batched Chamfer loss: uniform grid + in-warp brute-force fallback, 3 kernels.
// B=16, N=M=4096, 3D Gaussian points.
//
// bin_kernel:  per (set,b): count + shfl-scan + scatter in smem -> cell-sorted
//              folded points (-2x,-2y,-2z,|t|^2) + per-cell starts.
// solve_kernel: 8 blocks per (set,b); database (64KB) AND starts (32KB) staged
//              in smem. Each query scans its 3x3x3 cell cube from smem (exact
//              iff d^2 <= H^2-eps; all non-cube points are >= H away). The ~2%
//              unresolved lanes are solved immediately by the whole warp
//              brute-forcing the smem db with a shfl fminf tree. Block writes
//              one weighted partial sum.
// finalize:    deterministic reduction of 256 partials.

constexpr int   B_    = 16;
constexpr int   N_    = 4096;
constexpr int   G     = 20;
constexpr int   CELLS = G * G * G;          // 8000
constexpr float H     = 0.35f;
constexpr float X0    = -3.5f;              // G*H = 7.0 -> [-3.5, 3.5]
constexpr float INVH  = 1.0f / H;
constexpr float RES_T = H * H - 1e-4f;      // resolved threshold

constexpr int BIN_THREADS = 1024;
constexpr int PPT         = N_ / BIN_THREADS;   // 4

constexpr int SBLK   = 8;                   // solve blocks per (set,b)
constexpr int STHREADS = 512;               // == N_/SBLK queries per block
constexpr int NPART  = 2 * B_ * SBLK;       // 256 partials

// solve smem: db float4[4096] + starts int[CELLS+1] + red float[STHREADS]
constexpr int SMEM_DB     = N_ * 16;                    // 65536
constexpr int SMEM_STARTS = (CELLS + 1) * 4;            // 32004
constexpr int SMEM_SOLVE  = SMEM_DB + SMEM_STARTS + STHREADS * 4 + 16;

__device__ float4 g_binned[2 * B_ * N_];    // cell-sorted folded points
__device__ int    g_starts[2 * B_ * (CELLS + 1)];
__device__ float  g_partial[NPART];

__device__ __forceinline__ int cell_of(float v) {
    int c = (int)floorf((v - X0) * INVH);
    return min(max(c, 0), G - 1);
}

// ---------------- binning ----------------

__global__ void __launch_bounds__(BIN_THREADS)
bin_kernel(const float* __restrict__ src, const float* __restrict__ tgt)
{
    __shared__ int scnt[CELLS];             // counts -> write cursors
    __shared__ int s_wsum[32];

    const int sb  = blockIdx.x;             // 0..31 = set*16 + b
    const int set = sb >> 4, b = sb & 15;
    const float* __restrict__ pts = (set == 0 ? src : tgt) + (size_t)b * N_ * 3;
    const int t = threadIdx.x, lane = t & 31, wid = t >> 5;

#pragma unroll
    for (int i = 0; i < 8; ++i) {
        const int c = t * 8 + i;
        if (c < CELLS) scnt[c] = 0;
    }
    __syncthreads();

    float px[PPT], py[PPT], pz[PPT];
    int   pc[PPT];
#pragma unroll
    for (int r = 0; r < PPT; ++r) {
        const float* p = pts + (size_t)(r * BIN_THREADS + t) * 3;
        px[r] = p[0]; py[r] = p[1]; pz[r] = p[2];
        pc[r] = (cell_of(pz[r]) * G + cell_of(py[r])) * G + cell_of(px[r]);
        atomicAdd(&scnt[pc[r]], 1);
    }
    __syncthreads();

    // Exclusive scan over CELLS: 8 serial/thread + shfl warp scans.
    int local[8], sum = 0;
#pragma unroll
    for (int i = 0; i < 8; ++i) {
        const int c = t * 8 + i;
        local[i] = (c < CELLS) ? scnt[c] : 0;
        sum += local[i];
    }
    int incl = sum;
#pragma unroll
    for (int off = 1; off < 32; off <<= 1) {
        const int v = __shfl_up_sync(0xffffffffu, incl, off);
        if (lane >= off) incl += v;
    }
    if (lane == 31) s_wsum[wid] = incl;
    __syncthreads();
    if (wid == 0) {
        const int v = s_wsum[lane];
        int inc2 = v;
#pragma unroll
        for (int off = 1; off < 32; off <<= 1) {
            const int u = __shfl_up_sync(0xffffffffu, inc2, off);
            if (lane >= off) inc2 += u;
        }
        s_wsum[lane] = inc2 - v;            // exclusive warp offsets
    }
    __syncthreads();

    int run = s_wsum[wid] + incl - sum;     // thread's exclusive prefix
    int* starts = g_starts + sb * (CELLS + 1);
#pragma unroll
    for (int i = 0; i < 8; ++i) {
        const int c = t * 8 + i;
        if (c < CELLS) {
            starts[c] = run;
            scnt[c]   = run;                // smem becomes write cursor
            run += local[i];
        }
    }
    if (t == 0) starts[CELLS] = N_;
    __syncthreads();

#pragma unroll
    for (int r = 0; r < PPT; ++r) {
        const int pos = atomicAdd(&scnt[pc[r]], 1);
        g_binned[sb * N_ + pos] =
            make_float4(-2.0f * px[r], -2.0f * py[r], -2.0f * pz[r],
                        px[r] * px[r] + py[r] * py[r] + pz[r] * pz[r]);
    }
}

// ---------------- solve: cube scan + in-warp brute fallback ----------------

__global__ void __launch_bounds__(STHREADS)
solve_kernel(const float* __restrict__ weights)
{
    extern __shared__ char s_raw[];
    float4* s_db     = (float4*)s_raw;                      // [N_]
    int*    s_starts = (int*)(s_raw + SMEM_DB);             // [CELLS+1]
    float*  s_red    = (float*)(s_raw + SMEM_DB + SMEM_STARTS);

    const int sb   = blockIdx.y;            // query (set,b)
    const int dbsb = sb ^ 16;               // database (set,b)
    const int tid  = threadIdx.x;
    const int lane = tid & 31;

    // Stage database + starts (coalesced, L2-resident).
    for (int i = tid; i < N_; i += STHREADS)
        s_db[i] = g_binned[dbsb * N_ + i];
    for (int i = tid; i < CELLS + 1; i += STHREADS)
        s_starts[i] = g_starts[dbsb * (CELLS + 1) + i];
    __syncthreads();

    // One query per thread, in binned (cell-sorted) order -> warp-coherent.
    const int pos = blockIdx.x * STHREADS + tid;
    const float4 qt = g_binned[sb * N_ + pos];
    const float qx = -0.5f * qt.x, qy = -0.5f * qt.y, qz = -0.5f * qt.z;
    const float q2 = qt.w;

    const int cx = cell_of(qx), cy = cell_of(qy), cz = cell_of(qz);
    const int xlo = max(cx - 1, 0), xhi = min(cx + 1, G - 1);

    // Prefetch all 9 row ranges, then scan the 3x3x3 cube from smem.
    int p0[9], p1[9];
#pragma unroll
    for (int i = 0; i < 9; ++i) {
        const int z = cz + i / 3 - 1, y = cy + i % 3 - 1;
        const bool ok = ((unsigned)z < (unsigned)G) &
                        ((unsigned)y < (unsigned)G);
        const int zc = min(max(z, 0), G - 1);
        const int yc = min(max(y, 0), G - 1);
        const int rb = (zc * G + yc) * G;
        const int a  = s_starts[rb + xlo];
        const int e  = s_starts[rb + xhi + 1];
        p0[i] = ok ? a : 0;
        p1[i] = ok ? e : 0;
    }

    float dbest = FLT_MAX;                  // folded (= d^2 - q2)
#pragma unroll
    for (int i = 0; i < 9; ++i) {
        for (int p = p0[i]; p < p1[i]; ++p) {
            const float4 tp = s_db[p];
            dbest = fminf(dbest,
                    fmaf(qx, tp.x, fmaf(qy, tp.y, fmaf(qz, tp.z, tp.w))));
        }
    }

    float d2 = q2 + dbest;

    // In-warp exact fallback for unresolved lanes (~2%): whole warp scans the
    // smem database for one lane's query at a time; shfl fminf tree.
    unsigned um = __ballot_sync(0xffffffffu, !(d2 <= RES_T));
    while (um) {
        const int srcl = __ffs(um) - 1;
        um &= um - 1;
        const float bx = __shfl_sync(0xffffffffu, qx, srcl);
        const float by = __shfl_sync(0xffffffffu, qy, srcl);
        const float bz = __shfl_sync(0xffffffffu, qz, srcl);
        float m = FLT_MAX;
#pragma unroll 4
        for (int k = lane; k < N_; k += 32) {
            const float4 tp = s_db[k];
            m = fminf(m, fmaf(bx, tp.x, fmaf(by, tp.y, fmaf(bz, tp.z, tp.w))));
        }
#pragma unroll
        for (int off = 16; off > 0; off >>= 1)
            m = fminf(m, __shfl_xor_sync(0xffffffffu, m, off));
        if (lane == srcl) d2 = q2 + m;      // exact replacement
    }

    // Deterministic block reduction; fold this batch's weight.
    s_red[tid] = fmaxf(d2, 0.0f);
    __syncthreads();
#pragma unroll
    for (int st = STHREADS / 2; st > 0; st >>= 1) {
        if (tid < st) s_red[tid] += s_red[tid + st];
        __syncthreads();
    }
    if (tid == 0)
        g_partial[sb * SBLK + blockIdx.x] = s_red[0] * weights[sb & 15];
}

// ---------------- finalize ----------------

__global__ void __launch_bounds__(NPART)
finalize_kernel(float* __restrict__ out)
{
    const int t = threadIdx.x;              // 0..255
    __shared__ float s[NPART];
    s[t] = g_partial[t];
    __syncthreads();
#pragma unroll
    for (int st = NPART / 2; st > 0; st >>= 1) {
        if (t < st) s[t] += s[t + st];
        __syncthreads();
    }
    if (t == 0) out[0] = s[0] * (1.0f / (16.0f * 4096.0f));
}

extern "C" void kernel_launch(void* const* d_in, const int* in_sizes, int n_in,
                              void* d_out, int out_size)
{
    const float* src = (const float*)d_in[0];   // [16, 4096, 3]
    const float* tgt = (const float*)d_in[1];   // [16, 4096, 3]
    const float* w   = (const float*)d_in[2];   // [16]

    static bool attr_set = false;
    if (!attr_set) {
        cudaFuncSetAttribute(solve_kernel,
                             cudaFuncAttributeMaxDynamicSharedMemorySize,
                             SMEM_SOLVE);
        attr_set = true;
    }

    bin_kernel<<<2 * B_, BIN_THREADS>>>(src, tgt);
    solve_kernel<<<dim3(SBLK, 2 * B_), STHREADS, SMEM_SOLVE>>>(w);
    finalize_kernel<<<1, NPART>>>((float*)d_out);
}